// round 9
// baseline (speedup 1.0000x reference)
#include <cuda_runtime.h>

#define T_STEPS 1000
#define BATCH   512
#define INP     26
#define H1      64
#define H2      32
#define MB      4
#define NBLK    (BATCH / MB)
#define NTHR    768
#define KV      96            // K-vector length per layer (floats)

typedef unsigned long long ull;

// Scratch: x transposed to [t][b][i] for coalesced per-step reads.
__device__ float g_xT[T_STEPS * BATCH * INP];

// ---------- f32x2 helpers ----------
__device__ __forceinline__ ull pack2(float lo, float hi) {
    ull r; asm("mov.b64 %0, {%1, %2};" : "=l"(r) : "f"(lo), "f"(hi)); return r;
}
__device__ __forceinline__ void ffma2(ull& d, ull a, ull b) {
    asm("fma.rn.f32x2 %0, %1, %2, %0;" : "+l"(d) : "l"(a), "l"(b));
}
__device__ __forceinline__ float hsum2(ull v) {
    float lo, hi; asm("mov.b64 {%0, %1}, %2;" : "=f"(lo), "=f"(hi) : "l"(v)); return lo + hi;
}
__device__ __forceinline__ float ex2f(float x) { float y; asm("ex2.approx.f32 %0, %1;" : "=f"(y) : "f"(x)); return y; }
__device__ __forceinline__ float rcpf(float x) { float y; asm("rcp.approx.f32 %0, %1;" : "=f"(y) : "f"(x)); return y; }
// tanh(c) = 2*sigmoid(2c)-1
__device__ __forceinline__ float tanhc(float c) {
    return fmaf(2.0f, rcpf(1.0f + ex2f(-2.885390081777927f * c)), -1.0f);
}
// ---------- named barriers ----------
__device__ __forceinline__ void nbar_sync(int id, int cnt) {
    asm volatile("bar.sync %0, %1;" :: "r"(id), "r"(cnt) : "memory");
}
__device__ __forceinline__ void nbar_arrive(int id, int cnt) {
    asm volatile("bar.arrive %0, %1;" :: "r"(id), "r"(cnt) : "memory");
}
// interleaved offset of K-position k (0..95): chunk-of-4 m, quarter kq
__host__ __device__ __forceinline__ int ilv(int k) {
    int kq = k / 24, m = (k % 24) >> 2, j = k & 3;
    return (m * 4 + kq) * 4 + j;
}

// ---------- transpose x: [B,26,T] -> [T, B*26] ----------
__global__ void xpose_kernel(const float* __restrict__ x) {
    __shared__ float tile[32][33];
    int t0 = blockIdx.x * 32;
    int r0 = blockIdx.y * 32;
    int tx = threadIdx.x, ty = threadIdx.y;
#pragma unroll
    for (int k = 0; k < 4; k++) {
        int t = t0 + tx;
        int r = r0 + ty + k * 8;
        if (t < T_STEPS) tile[ty + k * 8][tx] = x[r * T_STEPS + t];
    }
    __syncthreads();
#pragma unroll
    for (int k = 0; k < 4; k++) {
        int t = t0 + ty + k * 8;
        int r = r0 + tx;
        if (t < T_STEPS) g_xT[t * (BATCH * INP) + r] = tile[tx][ty + k * 8];
    }
}

// L1 weight at padded-K index k (0..95): x[0..25], pad[26..31], h1[32..95]
__device__ __forceinline__ float wl1f(const float* wih, const float* whh, int row, int k) {
    return (k < INP) ? wih[row * INP + k] : ((k < 32) ? 0.0f : whh[row * H1 + (k - 32)]);
}
// L2 weight at K index k (0..95): h1[0..63], h2[64..95]
__device__ __forceinline__ float wl2f(const float* wih, const float* whh, int row, int k) {
    return (k < H1) ? wih[row * H1 + k] : whh[row * H2 + (k - H1)];
}

// Two interleaved operand buffers, ring depth 2:
//   b1[s][r][.] : L1 window [x(0..25)|pad|h1(32..95)], interleaved via ilv()
//   b2[s][r][.] : L2 window [h1(0..63)|h2(64..95)],   interleaved via ilv()
// L1 step t: reads b1[(t+1)&1], writes h1[t] -> b1[t&1] + b2[t&1], stages x[t+1] -> b1[t&1].
// L2 step t: reads b2[t&1], writes h2[t] -> b2[(t+1)&1].
// Bars: full[s]=2+s, empty[s]=4+s (count 768); bar1 = L1-internal (512); bar6 = L2 (256).
// Lane map: kq = lane&3, gate = (lane>>2)&3, us = lane>>4; thread owns units u0,u0+1.
__global__ __launch_bounds__(NTHR, 1)
void lstm_kernel(const float* __restrict__ w_ih1, const float* __restrict__ w_hh1,
                 const float* __restrict__ b_ih1, const float* __restrict__ b_hh1,
                 const float* __restrict__ w_ih2, const float* __restrict__ w_hh2,
                 const float* __restrict__ b_ih2, const float* __restrict__ b_hh2,
                 const float* __restrict__ w_fc1, const float* __restrict__ b_fc1,
                 const float* __restrict__ w_fc2, const float* __restrict__ b_fc2,
                 float* __restrict__ out) {
    __shared__ __align__(128) float b1[2][MB][KV];
    __shared__ __align__(128) float b2[2][MB][KV];
    __shared__ float fcs[MB][16];

    const int tid  = threadIdx.x;
    const int lane = tid & 31;
    const int wrp  = tid >> 5;
    const int b0   = blockIdx.x * MB;

    const bool isL1 = (wrp < 16);
    const int  wg   = isL1 ? wrp : wrp - 16;
    const int  kq   = lane & 3;
    const int  gt   = (lane >> 2) & 3;
    const int  us   = lane >> 4;
    const int  u0   = wg * 4 + us * 2;
    const int  Hd   = isL1 ? H1 : H2;
    const int  row0 = gt * Hd + u0;
    const int  row1 = row0 + 1;

    // ---- weights: 2 rows x 12 packed pairs (24-float K-quarter each) ----
    ull w0[12], w1[12];
    float bias0, bias1;
    if (isL1) {
#pragma unroll
        for (int m = 0; m < 12; m++) {
            int k = kq * 24 + 2 * m;
            w0[m] = pack2(wl1f(w_ih1, w_hh1, row0, k), wl1f(w_ih1, w_hh1, row0, k + 1));
            w1[m] = pack2(wl1f(w_ih1, w_hh1, row1, k), wl1f(w_ih1, w_hh1, row1, k + 1));
        }
        bias0 = b_ih1[row0] + b_hh1[row0];
        bias1 = b_ih1[row1] + b_hh1[row1];
    } else {
#pragma unroll
        for (int m = 0; m < 12; m++) {
            int k = kq * 24 + 2 * m;
            w0[m] = pack2(wl2f(w_ih2, w_hh2, row0, k), wl2f(w_ih2, w_hh2, row0, k + 1));
            w1[m] = pack2(wl2f(w_ih2, w_hh2, row1, k), wl2f(w_ih2, w_hh2, row1, k + 1));
        }
        bias0 = b_ih2[row0] + b_hh2[row0];
        bias1 = b_ih2[row1] + b_hh2[row1];
    }
    const float mact = (gt == 2) ? -2.885390081777927f : -1.4426950408889634f;
    const float aact = (gt == 2) ? 2.0f : 1.0f;
    const float bact = (gt == 2) ? -1.0f : 0.0f;

    // per-thread interleaved write offsets (owner lanes)
    const int offh1a = ilv(32 + u0);   // h1 in b1 window
    const int offh1b = ilv(u0);        // h1 in b2 window
    const int offh2  = ilv(64 + u0);   // h2 in b2 window

    float cs0 = 0.0f, cs1 = 0.0f;      // owner cells: rows u0,u0+1, batch r = kq

    // ---- zero buffers, overlay x[0] into b1 slot 1, prefetch x[1] ----
    for (int i = tid; i < 2 * MB * KV; i += NTHR) { ((float*)b1)[i] = 0.0f; ((float*)b2)[i] = 0.0f; }
    __syncthreads();
    float rx = 0.0f;
    const int r_p = tid / INP, i_p = tid - r_p * INP;
    const int xoff = ilv(i_p < INP ? i_p : 0);
    if (tid < MB * INP) {
        b1[1][r_p][xoff] = g_xT[b0 * INP + tid];
        rx = g_xT[BATCH * INP + b0 * INP + tid];
    }
    __syncthreads();

    if (isL1) {
        // ================= layer-1 producer =================
        for (int t = 0; t < T_STEPS; t++) {
            const float* __restrict__ sr = &b1[(t + 1) & 1][0][0];
            float* __restrict__ sw  = &b1[t & 1][0][0];
            float* __restrict__ sw2 = &b2[t & 1][0][0];

            // stage x[t+1]; prefetch x[t+2] (threads 0..103, all L1)
            if (tid < MB * INP) {
                if (t < T_STEPS - 1) sw[r_p * KV + xoff] = rx;
                if (t + 2 < T_STEPS) rx = g_xT[(t + 2) * (BATCH * INP) + b0 * INP + tid];
            }

            ull a0[4], a1[4];
#pragma unroll
            for (int r = 0; r < 4; r++) { a0[r] = 0; a1[r] = 0; }
#pragma unroll
            for (int r = 0; r < 4; r++) {
                const float* bp = sr + r * KV + kq * 4;
#pragma unroll
                for (int m = 0; m < 6; m++) {
                    ulonglong2 p = *(const ulonglong2*)(bp + m * 16);
                    ffma2(a0[r], w0[2 * m], p.x); ffma2(a0[r], w0[2 * m + 1], p.y);
                    ffma2(a1[r], w1[2 * m], p.x); ffma2(a1[r], w1[2 * m + 1], p.y);
                }
            }
            float s0[4], s1[4];
#pragma unroll
            for (int r = 0; r < 4; r++) { s0[r] = hsum2(a0[r]); s1[r] = hsum2(a1[r]); }
#pragma unroll
            for (int r = 0; r < 4; r++) {
                s0[r] += __shfl_xor_sync(0xffffffffu, s0[r], 1);
                s1[r] += __shfl_xor_sync(0xffffffffu, s1[r], 1);
            }
#pragma unroll
            for (int r = 0; r < 4; r++) {
                s0[r] += __shfl_xor_sync(0xffffffffu, s0[r], 2);
                s1[r] += __shfl_xor_sync(0xffffffffu, s1[r], 2);
            }
            // this lane activates batch r = kq
            float v0 = ((kq & 2) ? ((kq & 1) ? s0[3] : s0[2]) : ((kq & 1) ? s0[1] : s0[0])) + bias0;
            float v1 = ((kq & 2) ? ((kq & 1) ? s1[3] : s1[2]) : ((kq & 1) ? s1[1] : s1[0])) + bias1;
            float e0 = fmaf(aact, rcpf(1.0f + ex2f(mact * v0)), bact);
            float e1 = fmaf(aact, rcpf(1.0f + ex2f(mact * v1)), bact);

            const int gb = lane & ~12;
            float i0 = __shfl_sync(0xffffffffu, e0, gb);
            float f0 = __shfl_sync(0xffffffffu, e0, gb | 4);
            float g0 = __shfl_sync(0xffffffffu, e0, gb | 8);
            float o0 = __shfl_sync(0xffffffffu, e0, gb | 12);
            float i1 = __shfl_sync(0xffffffffu, e1, gb);
            float f1 = __shfl_sync(0xffffffffu, e1, gb | 4);
            float g1 = __shfl_sync(0xffffffffu, e1, gb | 8);
            float o1 = __shfl_sync(0xffffffffu, e1, gb | 12);

            float2 hq;
            if ((lane & 12) == 0) {
                float c;
                c = fmaf(f0, cs0, i0 * g0); cs0 = c; hq.x = o0 * tanhc(c);
                c = fmaf(f1, cs1, i1 * g1); cs1 = c; hq.y = o1 * tanhc(c);
            }
            if (t >= 2) nbar_sync(4 + (t & 1), NTHR);   // L2 done with b2 slot t&1
            if ((lane & 12) == 0) {
                *(float2*)&sw [kq * KV + offh1a] = hq;
                *(float2*)&sw2[kq * KV + offh1b] = hq;
            }
            nbar_arrive(2 + (t & 1), NTHR);             // publish h1[t]
            nbar_sync(1, 512);                          // L1-internal boundary
        }
    } else {
        // ================= layer-2 consumer =================
        for (int t = 0; t < T_STEPS; t++) {
            nbar_sync(2 + (t & 1), NTHR);               // wait for h1[t]
            const float* __restrict__ sr = &b2[t & 1][0][0];
            float* __restrict__ sw = &b2[(t + 1) & 1][0][0];

            ull a0[4], a1[4];
#pragma unroll
            for (int r = 0; r < 4; r++) { a0[r] = 0; a1[r] = 0; }
#pragma unroll
            for (int r = 0; r < 4; r++) {
                const float* bp = sr + r * KV + kq * 4;
#pragma unroll
                for (int m = 0; m < 6; m++) {
                    ulonglong2 p = *(const ulonglong2*)(bp + m * 16);
                    ffma2(a0[r], w0[2 * m], p.x); ffma2(a0[r], w0[2 * m + 1], p.y);
                    ffma2(a1[r], w1[2 * m], p.x); ffma2(a1[r], w1[2 * m + 1], p.y);
                }
            }
            nbar_arrive(4 + (t & 1), NTHR);             // done reading b2 slot t&1

            float s0[4], s1[4];
#pragma unroll
            for (int r = 0; r < 4; r++) { s0[r] = hsum2(a0[r]); s1[r] = hsum2(a1[r]); }
#pragma unroll
            for (int r = 0; r < 4; r++) {
                s0[r] += __shfl_xor_sync(0xffffffffu, s0[r], 1);
                s1[r] += __shfl_xor_sync(0xffffffffu, s1[r], 1);
            }
#pragma unroll
            for (int r = 0; r < 4; r++) {
                s0[r] += __shfl_xor_sync(0xffffffffu, s0[r], 2);
                s1[r] += __shfl_xor_sync(0xffffffffu, s1[r], 2);
            }
            float v0 = ((kq & 2) ? ((kq & 1) ? s0[3] : s0[2]) : ((kq & 1) ? s0[1] : s0[0])) + bias0;
            float v1 = ((kq & 2) ? ((kq & 1) ? s1[3] : s1[2]) : ((kq & 1) ? s1[1] : s1[0])) + bias1;
            float e0 = fmaf(aact, rcpf(1.0f + ex2f(mact * v0)), bact);
            float e1 = fmaf(aact, rcpf(1.0f + ex2f(mact * v1)), bact);

            const int gb = lane & ~12;
            float i0 = __shfl_sync(0xffffffffu, e0, gb);
            float f0 = __shfl_sync(0xffffffffu, e0, gb | 4);
            float g0 = __shfl_sync(0xffffffffu, e0, gb | 8);
            float o0 = __shfl_sync(0xffffffffu, e0, gb | 12);
            float i1 = __shfl_sync(0xffffffffu, e1, gb);
            float f1 = __shfl_sync(0xffffffffu, e1, gb | 4);
            float g1 = __shfl_sync(0xffffffffu, e1, gb | 8);
            float o1 = __shfl_sync(0xffffffffu, e1, gb | 12);

            if ((lane & 12) == 0) {
                float c;
                float2 hq;
                c = fmaf(f0, cs0, i0 * g0); cs0 = c; hq.x = o0 * tanhc(c);
                c = fmaf(f1, cs1, i1 * g1); cs1 = c; hq.y = o1 * tanhc(c);
                *(float2*)&sw[kq * KV + offh2] = hq;
            }
            nbar_sync(6, 256);                          // L2-internal boundary
        }
    }
    __syncthreads();

    // ===== FC head on final h2 (t=999 wrote into b2 slot 0, interleaved) =====
    if (tid < MB * 16) {
        int r = tid >> 4, q = tid & 15;
        float a = b_fc1[q];
#pragma unroll
        for (int k = 0; k < H2; k++) a += w_fc1[q * H2 + k] * b2[0][r][ilv(64 + k)];
        fcs[r][q] = fmaxf(a, 0.0f);
    }
    __syncthreads();
    if (tid < MB * 10) {
        int r = tid / 10, o = tid % 10;
        float a = b_fc2[o];
#pragma unroll
        for (int k = 0; k < 16; k++) a += w_fc2[o * 16 + k] * fcs[r][k];
        out[(b0 + r) * 10 + o] = a;
    }
}

extern "C" void kernel_launch(void* const* d_in, const int* in_sizes, int n_in,
                              void* d_out, int out_size) {
    const float* x     = (const float*)d_in[0];
    const float* w_ih1 = (const float*)d_in[1];
    const float* w_hh1 = (const float*)d_in[2];
    const float* b_ih1 = (const float*)d_in[3];
    const float* b_hh1 = (const float*)d_in[4];
    const float* w_ih2 = (const float*)d_in[5];
    const float* w_hh2 = (const float*)d_in[6];
    const float* b_ih2 = (const float*)d_in[7];
    const float* b_hh2 = (const float*)d_in[8];
    const float* w_fc1 = (const float*)d_in[9];
    const float* b_fc1 = (const float*)d_in[10];
    const float* w_fc2 = (const float*)d_in[11];
    const float* b_fc2 = (const float*)d_in[12];
    float* out = (float*)d_out;

    dim3 tb(32, 8);
    dim3 tg((T_STEPS + 31) / 32, (BATCH * INP) / 32);
    xpose_kernel<<<tg, tb>>>(x);

    lstm_kernel<<<NBLK, NTHR>>>(w_ih1, w_hh1, b_ih1, b_hh1,
                                w_ih2, w_hh2, b_ih2, b_hh2,
                                w_fc1, b_fc1, w_fc2, b_fc2, out);
}

// round 10
// speedup vs baseline: 1.5969x; 1.5969x over previous
#include <cuda_runtime.h>

#define T_STEPS 1000
#define BATCH   512
#define INP     26
#define H1      64
#define H2      32
#define MB      4
#define NBLK    (BATCH / MB)
#define NTHR    384
#define SSTR    128

typedef unsigned long long ull;

// Scratch: x transposed to [t][b][i] for coalesced per-step reads.
__device__ float g_xT[T_STEPS * BATCH * INP];

// ---------- f32x2 helpers ----------
__device__ __forceinline__ ull pack2(float lo, float hi) {
    ull r; asm("mov.b64 %0, {%1, %2};" : "=l"(r) : "f"(lo), "f"(hi)); return r;
}
__device__ __forceinline__ void ffma2(ull& d, ull a, ull b) {
    asm("fma.rn.f32x2 %0, %1, %2, %0;" : "+l"(d) : "l"(a), "l"(b));
}
__device__ __forceinline__ float hsum2(ull v) {
    float lo, hi; asm("mov.b64 {%0, %1}, %2;" : "=f"(lo), "=f"(hi) : "l"(v)); return lo + hi;
}
__device__ __forceinline__ float ex2f(float x) { float y; asm("ex2.approx.f32 %0, %1;" : "=f"(y) : "f"(x)); return y; }
__device__ __forceinline__ float rcpf(float x) { float y; asm("rcp.approx.f32 %0, %1;" : "=f"(y) : "f"(x)); return y; }
__device__ __forceinline__ float sigm(float x) { return rcpf(1.0f + ex2f(-1.4426950408889634f * x)); }
// tanh(x) = 2*sigmoid(2x)-1
__device__ __forceinline__ float tanhx(float x) {
    return fmaf(2.0f, rcpf(1.0f + ex2f(-2.885390081777927f * x)), -1.0f);
}
// ---------- named barriers ----------
__device__ __forceinline__ void nbar_sync(int id, int cnt) {
    asm volatile("bar.sync %0, %1;" :: "r"(id), "r"(cnt) : "memory");
}
__device__ __forceinline__ void nbar_arrive(int id, int cnt) {
    asm volatile("bar.arrive %0, %1;" :: "r"(id), "r"(cnt) : "memory");
}

// ---------- transpose x: [B,26,T] -> [T, B*26] ----------
__global__ void xpose_kernel(const float* __restrict__ x) {
    __shared__ float tile[32][33];
    int t0 = blockIdx.x * 32;
    int r0 = blockIdx.y * 32;
    int tx = threadIdx.x, ty = threadIdx.y;
#pragma unroll
    for (int k = 0; k < 4; k++) {
        int t = t0 + tx;
        int r = r0 + ty + k * 8;
        if (t < T_STEPS) tile[ty + k * 8][tx] = x[r * T_STEPS + t];
    }
    __syncthreads();
#pragma unroll
    for (int k = 0; k < 4; k++) {
        int t = t0 + ty + k * 8;
        int r = r0 + tx;
        if (t < T_STEPS) g_xT[t * (BATCH * INP) + r] = tile[tx][ty + k * 8];
    }
}

// L1 weight at padded-K index k (0..95): x[0..25], pad[26..31], h1[32..95]
__device__ __forceinline__ float wl1f(const float* wih, const float* whh, int row, int k) {
    return (k < INP) ? wih[row * INP + k] : ((k < 32) ? 0.0f : whh[row * H1 + (k - 32)]);
}
// L2 weight at K index k (0..95): h1[0..63], h2[64..95]
__device__ __forceinline__ float wl2f(const float* wih, const float* whh, int row, int k) {
    return (k < H1) ? wih[row * H1 + k] : whh[row * H2 + (k - H1)];
}

// Slot layout (per batch row, 128 floats): [0..31] x (pad 0), [32..95] h1, [96..127] h2.
// Ring depth 2. L1 step t: reads slot (t+1)&1, writes h1[t]+x[t+1] -> slot t&1.
// L2 step t: reads slot t&1 (h1[t], h2[t-1]), writes h2[t] -> slot (t+1)&1.
// Bars: full[s]=2+s, empty[s]=4+s (384); bar1 = L1-internal (256); bar6 = L2 (128).
// Lane map: kq = lane&3 (K-quarter & final batch owner), usub = lane>>2.
// Thread owns ALL 4 gate rows of unit u = wg*8+usub over its 24-float K-slice.
__global__ __launch_bounds__(NTHR, 1)
void lstm_kernel(const float* __restrict__ w_ih1, const float* __restrict__ w_hh1,
                 const float* __restrict__ b_ih1, const float* __restrict__ b_hh1,
                 const float* __restrict__ w_ih2, const float* __restrict__ w_hh2,
                 const float* __restrict__ b_ih2, const float* __restrict__ b_hh2,
                 const float* __restrict__ w_fc1, const float* __restrict__ b_fc1,
                 const float* __restrict__ w_fc2, const float* __restrict__ b_fc2,
                 float* __restrict__ out) {
    __shared__ __align__(16) float sb[2][MB][SSTR];
    __shared__ float fcs[MB][16];

    const int tid  = threadIdx.x;
    const int lane = tid & 31;
    const int wrp  = tid >> 5;
    const int b0   = blockIdx.x * MB;

    const bool isL1 = (wrp < 8);
    const int  wg   = isL1 ? wrp : wrp - 8;
    const int  kq   = lane & 3;
    const int  usub = lane >> 2;
    const int  u    = wg * 8 + usub;
    const int  Hd   = isL1 ? H1 : H2;
    const int  koff = (isL1 ? 0 : 32) + kq * 24;  // slot offset of this lane's K-slice
    const int  p0   = kq & 1;                      // stage-1 parity
    const int  q0   = (kq >> 1) & 1;               // stage-2 parity

    // ---- weights: 4 gate rows x 12 packed pairs (24-float K-quarter) ----
    ull wt[4][12];
    float bias[4];
#pragma unroll
    for (int g = 0; g < 4; g++) {
        int row = g * Hd + u;
        if (isL1) {
#pragma unroll
            for (int m = 0; m < 12; m++) {
                int k = kq * 24 + 2 * m;
                wt[g][m] = pack2(wl1f(w_ih1, w_hh1, row, k), wl1f(w_ih1, w_hh1, row, k + 1));
            }
            bias[g] = b_ih1[row] + b_hh1[row];
        } else {
#pragma unroll
            for (int m = 0; m < 12; m++) {
                int k = kq * 24 + 2 * m;
                wt[g][m] = pack2(wl2f(w_ih2, w_hh2, row, k), wl2f(w_ih2, w_hh2, row, k + 1));
            }
            bias[g] = b_ih2[row] + b_hh2[row];
        }
    }

    float cst = 0.0f;   // cell state of (unit u, batch kq)

    // ---- zero slots, overlay x[0] into slot 1, prefetch x[1] ----
    for (int i = tid; i < 2 * MB * SSTR; i += NTHR) ((float*)sb)[i] = 0.0f;
    __syncthreads();
    float rx = 0.0f;
    const int r_p = tid / INP, i_p = tid - r_p * INP;
    if (tid < MB * INP) {
        sb[1][r_p][i_p] = g_xT[b0 * INP + tid];
        rx = g_xT[BATCH * INP + b0 * INP + tid];
    }
    __syncthreads();

    const int hwr = (isL1 ? 32 : 96) + u;   // h write offset within batch row

    if (isL1) {
        // ================= layer-1 producer =================
        for (int t = 0; t < T_STEPS; t++) {
            const float* __restrict__ sr = &sb[(t + 1) & 1][0][0];
            float* __restrict__ sw = &sb[t & 1][0][0];

            // stage x[t+1]; prefetch x[t+2] (threads 0..103, all L1)
            if (tid < MB * INP) {
                if (t < T_STEPS - 1) sw[r_p * SSTR + i_p] = rx;
                if (t + 2 < T_STEPS) rx = g_xT[(t + 2) * (BATCH * INP) + b0 * INP + tid];
            }

            // ===== partial gates: 4 gate rows x 4 batch over 24-float K-slice
            ull acc[4][4];
#pragma unroll
            for (int g = 0; g < 4; g++)
#pragma unroll
                for (int r = 0; r < 4; r++)
                    acc[g][r] = (kq == 0) ? pack2(bias[g], 0.0f) : 0ull;
#pragma unroll
            for (int r = 0; r < 4; r++) {
                const float* bp = sr + r * SSTR + koff;
#pragma unroll
                for (int m = 0; m < 6; m++) {
                    ulonglong2 p = *(const ulonglong2*)(bp + m * 4);
#pragma unroll
                    for (int g = 0; g < 4; g++) {
                        ffma2(acc[g][r], wt[g][2 * m],     p.x);
                        ffma2(acc[g][r], wt[g][2 * m + 1], p.y);
                    }
                }
            }
            float s[4][4];
#pragma unroll
            for (int g = 0; g < 4; g++)
#pragma unroll
                for (int r = 0; r < 4; r++) s[g][r] = hsum2(acc[g][r]);

            // ===== stage 1 (xor 1): keep batch rows of own parity, 8 shfl
            float tk[4][2];
#pragma unroll
            for (int g = 0; g < 4; g++)
#pragma unroll
                for (int j = 0; j < 2; j++) {
                    float snd = p0 ? s[g][2 * j] : s[g][2 * j + 1];
                    float kp  = p0 ? s[g][2 * j + 1] : s[g][2 * j];
                    tk[g][j] = kp + __shfl_xor_sync(0xffffffffu, snd, 1);
                }
            // ===== stage 2 (xor 2): keep batch r = kq, 4 shfl
            float fullg[4];
#pragma unroll
            for (int g = 0; g < 4; g++) {
                float snd = q0 ? tk[g][0] : tk[g][1];
                float kp  = q0 ? tk[g][1] : tk[g][0];
                fullg[g] = kp + __shfl_xor_sync(0xffffffffu, snd, 2);
            }

            // ===== activations + cell update (all lanes own (u, batch kq))
            float iv = sigm(fullg[0]);
            float fv = sigm(fullg[1]);
            float gv = tanhx(fullg[2]);
            float ov = sigm(fullg[3]);
            float c  = fmaf(fv, cst, iv * gv);
            cst = c;
            float hv = ov * tanhx(c);

            if (t >= 2) nbar_sync(4 + (t & 1), NTHR);   // slot free (L2 read h1[t-2])
            sw[kq * SSTR + hwr] = hv;
            nbar_arrive(2 + (t & 1), NTHR);             // publish h1[t]
            nbar_sync(1, 256);                          // L1-internal boundary
        }
    } else {
        // ================= layer-2 consumer =================
        for (int t = 0; t < T_STEPS; t++) {
            nbar_sync(2 + (t & 1), NTHR);               // wait for h1[t]
            const float* __restrict__ sr = &sb[t & 1][0][0];
            float* __restrict__ sw = &sb[(t + 1) & 1][0][0];

            ull acc[4][4];
#pragma unroll
            for (int g = 0; g < 4; g++)
#pragma unroll
                for (int r = 0; r < 4; r++)
                    acc[g][r] = (kq == 0) ? pack2(bias[g], 0.0f) : 0ull;
#pragma unroll
            for (int r = 0; r < 4; r++) {
                const float* bp = sr + r * SSTR + koff;
#pragma unroll
                for (int m = 0; m < 6; m++) {
                    ulonglong2 p = *(const ulonglong2*)(bp + m * 4);
#pragma unroll
                    for (int g = 0; g < 4; g++) {
                        ffma2(acc[g][r], wt[g][2 * m],     p.x);
                        ffma2(acc[g][r], wt[g][2 * m + 1], p.y);
                    }
                }
            }
            nbar_arrive(4 + (t & 1), NTHR);             // done reading slot t&1

            float s[4][4];
#pragma unroll
            for (int g = 0; g < 4; g++)
#pragma unroll
                for (int r = 0; r < 4; r++) s[g][r] = hsum2(acc[g][r]);

            float tk[4][2];
#pragma unroll
            for (int g = 0; g < 4; g++)
#pragma unroll
                for (int j = 0; j < 2; j++) {
                    float snd = p0 ? s[g][2 * j] : s[g][2 * j + 1];
                    float kp  = p0 ? s[g][2 * j + 1] : s[g][2 * j];
                    tk[g][j] = kp + __shfl_xor_sync(0xffffffffu, snd, 1);
                }
            float fullg[4];
#pragma unroll
            for (int g = 0; g < 4; g++) {
                float snd = q0 ? tk[g][0] : tk[g][1];
                float kp  = q0 ? tk[g][1] : tk[g][0];
                fullg[g] = kp + __shfl_xor_sync(0xffffffffu, snd, 2);
            }

            float iv = sigm(fullg[0]);
            float fv = sigm(fullg[1]);
            float gv = tanhx(fullg[2]);
            float ov = sigm(fullg[3]);
            float c  = fmaf(fv, cst, iv * gv);
            cst = c;
            float hv = ov * tanhx(c);

            sw[kq * SSTR + hwr] = hv;                   // h2[t] -> slot (t+1)&1
            nbar_sync(6, 128);                          // L2-internal boundary
        }
    }
    __syncthreads();

    // ===== FC head on final h2 (t=999 wrote into slot 0, h2 region) =====
    if (tid < MB * 16) {
        int r = tid >> 4, q = tid & 15;
        float a = b_fc1[q];
#pragma unroll
        for (int k = 0; k < H2; k++) a += w_fc1[q * H2 + k] * sb[0][r][96 + k];
        fcs[r][q] = fmaxf(a, 0.0f);
    }
    __syncthreads();
    if (tid < MB * 10) {
        int r = tid / 10, o = tid % 10;
        float a = b_fc2[o];
#pragma unroll
        for (int k = 0; k < 16; k++) a += w_fc2[o * 16 + k] * fcs[r][k];
        out[(b0 + r) * 10 + o] = a;
    }
}

extern "C" void kernel_launch(void* const* d_in, const int* in_sizes, int n_in,
                              void* d_out, int out_size) {
    const float* x     = (const float*)d_in[0];
    const float* w_ih1 = (const float*)d_in[1];
    const float* w_hh1 = (const float*)d_in[2];
    const float* b_ih1 = (const float*)d_in[3];
    const float* b_hh1 = (const float*)d_in[4];
    const float* w_ih2 = (const float*)d_in[5];
    const float* w_hh2 = (const float*)d_in[6];
    const float* b_ih2 = (const float*)d_in[7];
    const float* b_hh2 = (const float*)d_in[8];
    const float* w_fc1 = (const float*)d_in[9];
    const float* b_fc1 = (const float*)d_in[10];
    const float* w_fc2 = (const float*)d_in[11];
    const float* b_fc2 = (const float*)d_in[12];
    float* out = (float*)d_out;

    dim3 tb(32, 8);
    dim3 tg((T_STEPS + 31) / 32, (BATCH * INP) / 32);
    xpose_kernel<<<tg, tb>>>(x);

    lstm_kernel<<<NBLK, NTHR>>>(w_ih1, w_hh1, b_ih1, b_hh1,
                                w_ih2, w_hh2, b_ih2, b_hh2,
                                w_fc1, b_fc1, w_fc2, b_fc2, out);
}